// round 3
// baseline (speedup 1.0000x reference)
#include <cuda_runtime.h>
#include <math.h>

#define NQ   6
#define DIM  64
#define TS   64
#define PAD  68

// Precomputed combined unitary (transposed layout: [j][i] = C[i][j]) and Mz = ZSIGN @ Wc^T ([o][i])
__device__ float g_CRT[DIM * DIM];
__device__ float g_CIT[DIM * DIM];
__device__ float g_MzT[5 * DIM];

// ring permutation composition: ring(i) = c0(c1(...c5(i)))
__device__ __forceinline__ int ring_map(int r, int i) {
    int v = i;
    for (int w = NQ - 1; w >= 0; --w) {
        int t = (w + r) % NQ;
        v ^= ((v >> (NQ - 1 - w)) & 1) << (NQ - 1 - t);
    }
    return v;
}

// One block, 64 threads. Thread j owns column j of C (gates only mix rows -> columns independent).
__global__ void setup_kernel(const float* __restrict__ th_sh,
                             const float* __restrict__ th_tk,
                             const float* __restrict__ Wc) {
    __shared__ float2 C[DIM][DIM];   // C[i][j]
    int j = threadIdx.x;
    if (j >= DIM) return;
    for (int i = 0; i < DIM; i++) C[i][j] = make_float2(i == j ? 1.f : 0.f, 0.f);

    const float* TH[3] = { th_sh, th_sh + NQ * 3, th_tk };
    const int    RS[3] = { 1, 2, 1 };

    for (int l = 0; l < 3; l++) {
        const float* th = TH[l];
        for (int w = 0; w < NQ; w++) {
            float phi = th[w * 3 + 0], te = th[w * 3 + 1], om = th[w * 3 + 2];
            float sth, cth; sincosf(0.5f * te, &sth, &cth);
            float a = 0.5f * (phi + om), b = 0.5f * (phi - om);
            float sa, ca, sb, cb;
            sincosf(a, &sa, &ca);
            sincosf(b, &sb, &cb);
            // em = ca - i sa ; ep = cb + i sb
            float2 R00 = make_float2( ca * cth, -sa * cth);  // em*c
            float2 R01 = make_float2(-cb * sth, -sb * sth);  // -ep*s
            float2 R10 = make_float2( cb * sth, -sb * sth);  // conj(ep)*s
            float2 R11 = make_float2( ca * cth,  sa * cth);  // conj(em)*c
            int bit = 1 << (NQ - 1 - w);
            for (int i0 = 0; i0 < DIM; i0++) {
                if (i0 & bit) continue;
                int i1 = i0 | bit;
                float2 v0 = C[i0][j], v1 = C[i1][j];
                C[i0][j] = make_float2(
                    R00.x * v0.x - R00.y * v0.y + R01.x * v1.x - R01.y * v1.y,
                    R00.x * v0.y + R00.y * v0.x + R01.x * v1.y + R01.y * v1.x);
                C[i1][j] = make_float2(
                    R10.x * v0.x - R10.y * v0.y + R11.x * v1.x - R11.y * v1.y,
                    R10.x * v0.y + R10.y * v0.x + R11.x * v1.y + R11.y * v1.x);
            }
        }
        // row permutation: newC[i][:] = C[ring[i]][:]
        float2 tmp[DIM];
        for (int i = 0; i < DIM; i++) tmp[i] = C[ring_map(RS[l], i)][j];
        for (int i = 0; i < DIM; i++) C[i][j] = tmp[i];
    }
    for (int i = 0; i < DIM; i++) {
        g_CRT[j * DIM + i] = C[i][j].x;
        g_CIT[j * DIM + i] = C[i][j].y;
    }
    // Mz[i][o] = sum_q zsign(i,q) * Wc[o][q]   (thread j computes row i=j, stored [o][i])
    for (int o = 0; o < 5; o++) {
        float s = 0.f;
        for (int q = 0; q < NQ; q++) {
            float zs = ((j >> (NQ - 1 - q)) & 1) ? -1.f : 1.f;
            s += zs * Wc[o * NQ + q];
        }
        g_MzT[o * DIM + j] = s;
    }
}

__global__ __launch_bounds__(256, 2)
void qmaml_main_kernel(const float* __restrict__ x,
                       const float* __restrict__ W1,
                       const float* __restrict__ b1,
                       const float* __restrict__ lng,
                       const float* __restrict__ lnb,
                       const float* __restrict__ W2,
                       const float* __restrict__ b2,
                       const float* __restrict__ bc,
                       float* __restrict__ out,
                       int nTiles) {
    extern __shared__ float sm[];
    float* sW1T = sm;                       // [j][i]  W1[i][j]
    float* sCRT = sW1T + DIM * PAD;         // [j][i]
    float* sCIT = sCRT + DIM * PAD;         // [j][i]
    float* sA   = sCIT + DIM * PAD;         // XT [j][s], later prob [s][i]
    float* sB   = sA   + DIM * PAD;         // H [s][i], later psi0T [j][s]
    float* sVec = sB   + DIM * PAD;         // [s][q][2]  (64*12)
    float* sW2  = sVec + DIM * 12;          // [q][i]   (6*64)
    float* sMzT = sW2  + 6 * DIM;           // [o][i]   (5*64)
    float* sB1  = sMzT + 5 * DIM;           // 64
    float* sLnG = sB1  + DIM;               // 64
    float* sLnB = sLnG + DIM;               // 64
    float* sB2  = sLnB + DIM;               // 6
    float* sBc  = sB2  + 6;                 // 5

    const int tid = threadIdx.x;

    // ---- load weights once per block ----
    for (int idx = tid; idx < DIM * DIM; idx += 256) {
        int r = idx >> 6, c = idx & 63;
        sW1T[c * PAD + r] = W1[idx];        // W1 row-major [i][j] -> [j][i]
        sCRT[r * PAD + c] = g_CRT[idx];     // already [j][i]
        sCIT[r * PAD + c] = g_CIT[idx];
    }
    for (int idx = tid; idx < 6 * DIM; idx += 256) sW2[idx] = W2[idx];
    for (int idx = tid; idx < 5 * DIM; idx += 256) sMzT[idx] = g_MzT[idx];
    if (tid < DIM) { sB1[tid] = b1[tid]; sLnG[tid] = lng[tid]; sLnB[tid] = lnb[tid]; }
    if (tid < 6) sB2[tid] = b2[tid];
    if (tid < 5) sBc[tid] = bc[tid];
    __syncthreads();

    const int tx = tid & 15, ty = tid >> 4;
    const int s0 = ty * 4, i0 = tx * 4;

    for (int tile = blockIdx.x; tile < nTiles; tile += gridDim.x) {
        const float* xt = x + (size_t)tile * TS * DIM;

        // ---- load X tile transposed: sA[j][s] ----
        for (int idx = tid; idx < TS * DIM; idx += 256) {
            int s = idx >> 6, jj = idx & 63;
            sA[jj * PAD + s] = xt[idx];
        }
        __syncthreads();

        // ---- GEMM1: H[s][i] = relu(sum_j X[s][j] W1[i][j] + b1[i]) ----
        {
            float acc[4][4];
            #pragma unroll
            for (int k = 0; k < 4; k++)
                #pragma unroll
                for (int m = 0; m < 4; m++) acc[k][m] = 0.f;
            #pragma unroll 8
            for (int j = 0; j < DIM; j++) {
                float4 a = *(const float4*)(sA   + j * PAD + s0);
                float4 b = *(const float4*)(sW1T + j * PAD + i0);
                float av[4] = { a.x, a.y, a.z, a.w };
                float bv[4] = { b.x, b.y, b.z, b.w };
                #pragma unroll
                for (int k = 0; k < 4; k++)
                    #pragma unroll
                    for (int m = 0; m < 4; m++) acc[k][m] += av[k] * bv[m];
            }
            #pragma unroll
            for (int k = 0; k < 4; k++)
                #pragma unroll
                for (int m = 0; m < 4; m++) {
                    float h = acc[k][m] + sB1[i0 + m];
                    sB[(s0 + k) * PAD + i0 + m] = fmaxf(h, 0.f);
                }
        }
        __syncthreads();

        // ---- LayerNorm per sample (in place on sB) ----
        if (tid < TS) {
            float* row = sB + tid * PAD;
            float su = 0.f, sq = 0.f;
            #pragma unroll 8
            for (int i = 0; i < DIM; i++) { float v = row[i]; su += v; sq += v * v; }
            float mu  = su * (1.f / DIM);
            float var = sq * (1.f / DIM) - mu * mu;
            float inv = rsqrtf(var + 1e-5f);
            #pragma unroll 8
            for (int i = 0; i < DIM; i++)
                row[i] = (row[i] - mu) * inv * sLnG[i] + sLnB[i];
        }
        __syncthreads();

        // ---- z = tanh(H @ W2^T + b2); vec = (cos, sin)(pi/2 * z) ----
        for (int p = tid; p < TS * NQ; p += 256) {
            int s = p / NQ, q = p - s * NQ;
            const float* row = sB + s * PAD;
            const float* w2  = sW2 + q * DIM;
            float d = sB2[q];
            #pragma unroll 8
            for (int i = 0; i < DIM; i++) d += row[i] * w2[i];
            float z    = tanhf(d);
            float half = 1.5707963267948966f * z;
            float sn, cs;
            __sincosf(half, &sn, &cs);
            sVec[s * 12 + q * 2 + 0] = cs;
            sVec[s * 12 + q * 2 + 1] = sn;
        }
        __syncthreads();

        // ---- psi0[s][j] = prod_q vec[s][q][bit_q(j)], stored transposed sB[j][s] ----
        {
            int s = tid >> 2, jb = (tid & 3) << 4;
            float v[NQ][2];
            #pragma unroll
            for (int q = 0; q < NQ; q++) {
                v[q][0] = sVec[s * 12 + q * 2 + 0];
                v[q][1] = sVec[s * 12 + q * 2 + 1];
            }
            #pragma unroll
            for (int j2 = 0; j2 < 16; j2++) {
                int jj = jb + j2;
                float p = v[0][(jj >> 5) & 1];
                p *= v[1][(jj >> 4) & 1];
                p *= v[2][(jj >> 3) & 1];
                p *= v[3][(jj >> 2) & 1];
                p *= v[4][(jj >> 1) & 1];
                p *= v[5][ jj       & 1];
                sB[jj * PAD + s] = p;
            }
        }
        __syncthreads();

        // ---- GEMM2/3: psiR/psiI = psi0 @ C^T ; probs -> sA[s][i] ----
        {
            float aR[4][4], aI[4][4];
            #pragma unroll
            for (int k = 0; k < 4; k++)
                #pragma unroll
                for (int m = 0; m < 4; m++) { aR[k][m] = 0.f; aI[k][m] = 0.f; }
            #pragma unroll 4
            for (int j = 0; j < DIM; j++) {
                float4 a  = *(const float4*)(sB   + j * PAD + s0);
                float4 br = *(const float4*)(sCRT + j * PAD + i0);
                float4 bi = *(const float4*)(sCIT + j * PAD + i0);
                float av[4]  = { a.x,  a.y,  a.z,  a.w  };
                float brv[4] = { br.x, br.y, br.z, br.w };
                float biv[4] = { bi.x, bi.y, bi.z, bi.w };
                #pragma unroll
                for (int k = 0; k < 4; k++)
                    #pragma unroll
                    for (int m = 0; m < 4; m++) {
                        aR[k][m] += av[k] * brv[m];
                        aI[k][m] += av[k] * biv[m];
                    }
            }
            #pragma unroll
            for (int k = 0; k < 4; k++)
                #pragma unroll
                for (int m = 0; m < 4; m++)
                    sA[(s0 + k) * PAD + i0 + m] =
                        aR[k][m] * aR[k][m] + aI[k][m] * aI[k][m];
        }
        __syncthreads();

        // ---- out[s][o] = probs[s][:] . Mz[:][o] + bc[o] ----
        for (int p = tid; p < TS * 5; p += 256) {
            int s = p / 5, o = p - s * 5;
            const float* pr = sA + s * PAD;
            const float* mz = sMzT + o * DIM;
            float d = sBc[o];
            #pragma unroll 8
            for (int i = 0; i < DIM; i++) d += pr[i] * mz[i];
            out[((size_t)tile * TS + s) * 5 + o] = d;
        }
        __syncthreads();  // protect sA/sB before next tile overwrites
    }
}

extern "C" void kernel_launch(void* const* d_in, const int* in_sizes, int n_in,
                              void* d_out, int out_size) {
    const float* x     = (const float*)d_in[0];
    const float* W1    = (const float*)d_in[1];
    const float* b1    = (const float*)d_in[2];
    const float* ln_g  = (const float*)d_in[3];
    const float* ln_b  = (const float*)d_in[4];
    const float* W2    = (const float*)d_in[5];
    const float* b2    = (const float*)d_in[6];
    const float* th_sh = (const float*)d_in[7];
    const float* th_tk = (const float*)d_in[8];
    const float* Wc    = (const float*)d_in[9];
    const float* bc    = (const float*)d_in[10];
    float* out = (float*)d_out;

    int B = in_sizes[0] / DIM;
    int nTiles = B / TS;

    setup_kernel<<<1, 64>>>(th_sh, th_tk, Wc);

    size_t smem_floats = 5u * DIM * PAD + DIM * 12 + 6 * DIM + 5 * DIM + 3 * DIM + 6 + 5;
    size_t smem = smem_floats * sizeof(float);
    cudaFuncSetAttribute(qmaml_main_kernel,
                         cudaFuncAttributeMaxDynamicSharedMemorySize, (int)smem);

    int grid = 296;
    if (grid > nTiles) grid = nTiles;
    qmaml_main_kernel<<<grid, 256, smem>>>(x, W1, b1, ln_g, ln_b, W2, b2, bc,
                                           out, nTiles);
}